// round 8
// baseline (speedup 1.0000x reference)
#include <cuda_runtime.h>

// Ping-pong scratch (device globals — no allocation allowed).
__device__ float g_buf1[4 * 3 * 96  * 128];   // stage1 out
__device__ float g_buf2[4 * 3 * 192 * 256];   // stage2 out
__device__ float g_buf3[4 * 3 * 384 * 512];   // stage3 out

// One convex-upsample stage (scale=2). Thread = one SOURCE pixel (n,h,w) and
// ONE subpixel row i (blockIdx.y = n*2+i): computes output pixels
// (2h+i, 2w+0) and (2h+i, 2w+1) for all 3 channels.
// Half the per-thread state of the quad kernel -> ~34 regs -> high occupancy,
// double the warps for latency hiding. Neighbor gathers are duplicated 2x
// across the i-halves but are small L2-resident reads.
// mask layout [N,36,H,W], channel c = k*4 + i*2 + j.
// Softmax over k without max-subtraction (exp of ~N(0,1) safe; identical result).
template<int H, int WSHIFT, bool FIRST, int TPB, int MINB>
__global__ __launch_bounds__(TPB, MINB)
void convex_up_half(const float* __restrict__ in_flow,
                    const float* __restrict__ in_dz,
                    const float* __restrict__ mask,
                    float* __restrict__ out)
{
    constexpr int W  = 1 << WSHIFT;
    constexpr int HW = H * W;

    const int idx = blockIdx.x * TPB + threadIdx.x;   // grid exact: no guard
    const int ni  = blockIdx.y;                        // n*2 + i
    const int n   = ni >> 1;
    const int i   = ni & 1;
    const int w = idx & (W - 1);
    const int h = idx >> WSHIFT;

    // base for channels k*4 + i*2 + {0,1}; k-offsets are compile-time consts.
    const float* mb = mask + (size_t)n * (36 * HW) + (size_t)(i * 2) * HW + idx;
    const float* pf = in_flow + (size_t)n * (FIRST ? 2 * HW : 3 * HW);
    const float* pd = in_dz   + (size_t)n * (FIRST ?     HW : 3 * HW);

    // Hoisted edge predicates.
    const bool okl = (w > 0), okr = (w + 1 < W);
    const bool oku = (h > 0), okd = (h + 1 < H);

    float s0 = 0.f, s1 = 0.f;
    float a0[3] = {0.f, 0.f, 0.f};
    float a1[3] = {0.f, 0.f, 0.f};

#pragma unroll
    for (int k = 0; k < 9; k++) {
        const int dy = k / 3 - 1;
        const int dx = k % 3 - 1;
        const bool ok = (dy == 0 || (dy < 0 ? oku : okd)) &&
                        (dx == 0 || (dx < 0 ? okl : okr));
        float v0 = 0.f, v1 = 0.f, v2 = 0.f;
        if (ok) {
            const int off = ((h + dy) << WSHIFT) + (w + dx);
            v0 = pf[off];
            v1 = pf[off + HW];
            v2 = pd[off];
        }
        float e0 = __expf(__ldcs(mb + (size_t)(k * 4 + 0) * HW));
        float e1 = __expf(__ldcs(mb + (size_t)(k * 4 + 1) * HW));
        s0 += e0; s1 += e1;
        a0[0] = fmaf(e0, v0, a0[0]);  a1[0] = fmaf(e1, v0, a1[0]);
        a0[1] = fmaf(e0, v1, a0[1]);  a1[1] = fmaf(e1, v1, a1[1]);
        a0[2] = fmaf(e0, v2, a0[2]);  a1[2] = fmaf(e1, v2, a1[2]);
    }

    const float r0 = __fdividef(1.0f, s0);
    const float r1 = __fdividef(1.0f, s1);

    // out [N,3,2H,2W]; row 2h+i, cols 2w..2w+1; float2 store per channel.
    constexpr int W2 = W << 1;
    constexpr size_t HW4 = (size_t)HW * 4;
    float* ob = out + (size_t)n * (3 * HW4)
                    + (size_t)((h << 1) + i) * W2 + (w << 1);
#pragma unroll
    for (int ch = 0; ch < 3; ch++) {
        const float pm = (ch < 2) ? 2.0f : 1.0f;   // flow premul per stage
        float2 v;
        v.x = pm * a0[ch] * r0;
        v.y = pm * a1[ch] * r1;
        *reinterpret_cast<float2*>(ob + (size_t)ch * HW4) = v;
    }
}

template<int H, int WSHIFT, bool FIRST, int TPB, int MINB>
static inline void launch_stage(const float* pf, const float* pd,
                                const float* mask, float* out, int N)
{
    constexpr int HW = H << WSHIFT;
    static_assert(HW % TPB == 0, "exact grid");
    dim3 grid(HW / TPB, N * 2);   // y = n*2 + i
    convex_up_half<H, WSHIFT, FIRST, TPB, MINB><<<grid, TPB>>>(pf, pd, mask, out);
}

extern "C" void kernel_launch(void* const* d_in, const int* in_sizes, int n_in,
                              void* d_out, int out_size)
{
    const float* flow16 = (const float*)d_in[0];  // [4,2,48,64]
    const float* dz16   = (const float*)d_in[1];  // [4,1,48,64]
    const float* mask16 = (const float*)d_in[2];  // [4,36,48,64]
    const float* mask8  = (const float*)d_in[3];  // [4,36,96,128]
    const float* mask4  = (const float*)d_in[4];  // [4,36,192,256]
    const float* mask2  = (const float*)d_in[5];  // [4,36,384,512]
    float* out = (float*)d_out;                   // [4,3,768,1024]

    float *buf1, *buf2, *buf3;
    cudaGetSymbolAddress((void**)&buf1, g_buf1);
    cudaGetSymbolAddress((void**)&buf2, g_buf2);
    cudaGetSymbolAddress((void**)&buf3, g_buf3);

    const int N = 4;

    // Stage 1: 48x64 -> 96x128. 64-thr blocks -> 384 CTAs (fill the chip).
    launch_stage<48, 6, true, 64, 16>(flow16, dz16, mask16, buf1, N);
    // Stage 2: 96x128 -> 192x256. 64-thr blocks -> 1536 CTAs.
    launch_stage<96, 7, false, 64, 16>(buf1, buf1 + 2 * 96 * 128, mask8, buf2, N);
    // Stage 3: 192x256 -> 384x512.
    launch_stage<192, 8, false, 256, 6>(buf2, buf2 + 2 * 192 * 256, mask4, buf3, N);
    // Stage 4: 384x512 -> 768x1024.
    launch_stage<384, 9, false, 256, 6>(buf3, buf3 + 2 * 384 * 512, mask2, out, N);
}